// round 2
// baseline (speedup 1.0000x reference)
#include <cuda_runtime.h>

#define TOKENS 131072
#define KCODES 512
#define DIM    64
#define TPB    512
#define NBLK   (TOKENS / TPB)   /* 256 */

// smem: codebook 512*64 f32 | wsq 512 f32 | hist 512 int | warp-red 16 f32
#define SMEM_W_FLOATS   (KCODES * DIM)
#define SMEM_BYTES      ((SMEM_W_FLOATS + KCODES) * 4 + KCODES * 4 + 64)

__device__ int   g_counts[KCODES];
__device__ float g_msep[NBLK];

#define FMA2(d, a, b, c) \
    asm("fma.rn.f32x2 %0, %1, %2, %3;" : "=l"(d) : "l"(a), "l"(b), "l"(c))

__global__ void vq_init()
{
    if (threadIdx.x < KCODES) g_counts[threadIdx.x] = 0;
}

__global__ void __launch_bounds__(TPB, 1)
vq_main(const float* __restrict__ x, const float* __restrict__ w,
        float* __restrict__ out)
{
    extern __shared__ float smem[];
    float* sw    = smem;                         // [512][64]
    float* swsq  = smem + SMEM_W_FLOATS;         // [512]
    int*   shist = (int*)(swsq + KCODES);        // [512]
    float* sred  = (float*)(shist + KCODES);     // [16]

    const int tid = threadIdx.x;

    // ---- cooperative codebook load (float4, 128 KB) ----
    {
        const float4* wg = (const float4*)w;
        float4* s4 = (float4*)sw;
        #pragma unroll
        for (int i = tid; i < SMEM_W_FLOATS / 4; i += TPB) s4[i] = wg[i];
    }
    shist[tid] = 0;                              // TPB == KCODES
    __syncthreads();

    // ---- per-code squared norms (sequential over d, matches jnp.sum order) ----
    {
        const float* r = sw + tid * DIM;
        float sq = 0.f;
        #pragma unroll
        for (int d = 0; d < DIM; d++) sq = fmaf(r[d], r[d], sq);
        swsq[tid] = sq;
    }
    __syncthreads();

    // ---- gather this thread's token (NHWC gather from NCHW) ----
    const int g  = blockIdx.x * TPB + tid;      // flat token id
    const int b  = g >> 12;                      // / (64*64)
    const int hw = g & 4095;
    const float* xb = x + (size_t)b * (DIM * 4096) + hw;

    unsigned long long X[DIM / 2];              // x packed as f32x2
    float s = 0.f;                               // sum(x*x)
    #pragma unroll
    for (int i = 0; i < DIM / 2; i++) {
        float x0 = xb[(size_t)(2 * i)     * 4096];
        float x1 = xb[(size_t)(2 * i + 1) * 4096];
        s = fmaf(x0, x0, s);
        s = fmaf(x1, x1, s);
        asm("mov.b64 %0, {%1, %2};" : "=l"(X[i]) : "f"(x0), "f"(x1));
    }

    // ---- argmin over 512 codes: dist = (s - 2*dot) + ||w_k||^2 ----
    float best = __int_as_float(0x7f800000);    // +inf
    int   bidx = 0;
    #pragma unroll 2
    for (int k = 0; k < KCODES; k++) {
        const float4* wr = (const float4*)(sw + k * DIM);
        unsigned long long acc = 0ull;          // (0.f, 0.f)
        #pragma unroll
        for (int i = 0; i < DIM / 4; i++) {
            float4 wv = wr[i];                  // broadcast LDS.128, conflict-free
            unsigned long long w01, w23;
            asm("mov.b64 %0, {%1, %2};" : "=l"(w01) : "f"(wv.x), "f"(wv.y));
            asm("mov.b64 %0, {%1, %2};" : "=l"(w23) : "f"(wv.z), "f"(wv.w));
            FMA2(acc, X[2 * i],     w01, acc);
            FMA2(acc, X[2 * i + 1], w23, acc);
        }
        float lo, hi;
        asm("mov.b64 {%0, %1}, %2;" : "=f"(lo), "=f"(hi) : "l"(acc));
        float dot  = lo + hi;
        float dist = fmaf(-2.f, dot, s) + swsq[k];
        if (dist < best) { best = dist; bidx = k; }   // strict <: first-min tie rule
    }

    // ---- epilogue: out row g = x_lin + (w[bidx] - x_lin) where x_lin is the
    //      NCHW-linear view (faithful to the reference's missing inverse
    //      permute); fused MSE partial ----
    const float4* wbest = (const float4*)(sw + bidx * DIM);
    const float4* xl    = (const float4*)(x + (size_t)g * DIM);
    float4*       o4    = (float4*)(out + (size_t)g * DIM);
    float mse = 0.f;
    #pragma unroll
    for (int i = 0; i < DIM / 4; i++) {
        float4 wv = wbest[i];
        float4 xv = xl[i];
        float d0 = wv.x - xv.x, d1 = wv.y - xv.y;
        float d2 = wv.z - xv.z, d3 = wv.w - xv.w;
        mse = fmaf(d0, d0, mse); mse = fmaf(d1, d1, mse);
        mse = fmaf(d2, d2, mse); mse = fmaf(d3, d3, mse);
        float4 ov;
        ov.x = xv.x + d0; ov.y = xv.y + d1;
        ov.z = xv.z + d2; ov.w = xv.w + d3;
        o4[i] = ov;
    }

    atomicAdd(&shist[bidx], 1);

    // ---- deterministic block MSE reduce ----
    #pragma unroll
    for (int o = 16; o > 0; o >>= 1)
        mse += __shfl_xor_sync(0xffffffffu, mse, o);
    if ((tid & 31) == 0) sred[tid >> 5] = mse;
    __syncthreads();
    if (tid == 0) {
        float t = 0.f;
        #pragma unroll
        for (int i = 0; i < TPB / 32; i++) t += sred[i];
        g_msep[blockIdx.x] = t;
    }
    // ---- flush histogram (int atomics: deterministic) ----
    {
        int c = shist[tid];
        if (c) atomicAdd(&g_counts[tid], c);
    }
}

__global__ void __launch_bounds__(TPB, 1)
vq_final(float* __restrict__ out)
{
    __shared__ float sred[16];
    const int tid = threadIdx.x;

    // loss = 1.25 * mean((q - x)^2)
    float m = (tid < NBLK) ? g_msep[tid] : 0.f;
    #pragma unroll
    for (int o = 16; o > 0; o >>= 1)
        m += __shfl_xor_sync(0xffffffffu, m, o);
    if ((tid & 31) == 0) sred[tid >> 5] = m;
    __syncthreads();
    float mt = 0.f;
    if (tid == 0) {
        #pragma unroll
        for (int i = 0; i < TPB / 32; i++) mt += sred[i];
    }
    __syncthreads();

    // perplexity = exp(-sum p*log(p + 1e-10))
    float p = (float)g_counts[tid] * (1.0f / (float)TOKENS);
    float e = p * logf(p + 1e-10f);
    #pragma unroll
    for (int o = 16; o > 0; o >>= 1)
        e += __shfl_xor_sync(0xffffffffu, e, o);
    if ((tid & 31) == 0) sred[tid >> 5] = e;
    __syncthreads();
    if (tid == 0) {
        float et = 0.f;
        #pragma unroll
        for (int i = 0; i < TPB / 32; i++) et += sred[i];
        out[(size_t)TOKENS * DIM]     = 1.25f * (mt / (float)(TOKENS * DIM));
        out[(size_t)TOKENS * DIM + 1] = expf(-et);
    }
}

extern "C" void kernel_launch(void* const* d_in, const int* in_sizes, int n_in,
                              void* d_out, int out_size)
{
    const float* x = (const float*)d_in[0];
    const float* w = (const float*)d_in[1];
    // defensive: accept either metadata order (shapes are unambiguous)
    if (n_in >= 2 && in_sizes[0] == KCODES * DIM && in_sizes[1] == TOKENS * DIM) {
        const float* t = x; x = w; w = t;
    }
    float* out = (float*)d_out;

    (void)cudaFuncSetAttribute(vq_main,
                               cudaFuncAttributeMaxDynamicSharedMemorySize,
                               SMEM_BYTES);

    vq_init<<<1, TPB>>>();
    vq_main<<<NBLK, TPB, SMEM_BYTES>>>(x, w, out);
    vq_final<<<1, TPB>>>(out);
}

// round 5
// speedup vs baseline: 1.3772x; 1.3772x over previous
#include <cuda_runtime.h>
#include <cstdint>

#define TOKENS  131072
#define KCODES  512
#define DIM     64
#define TILE_M  128
#define NTILES  (TOKENS / TILE_M)   /* 1024 */
#define NCTA    148
#define TPB     256
#define NHALF   256                  /* codes per half */
#define MAXSLOT 7

/* ---- smem layout (bytes) ---- */
/* B half, packed quads: row stride 36 x 16B = 576 B, 256 rows */
#define SM_B     0
#define SM_AH    147456                     /* 128 rows x 68 floats */
#define SM_AL    (SM_AH + 34816)
#define SM_WSQ   (SM_AL + 34816)            /* 512 f32            */
#define SM_SX    (SM_WSQ + 2048)            /* 128 f32            */
#define SM_BEST  (SM_SX + 512)              /* 896 f32            */
#define SM_IDX   (SM_BEST + 3584)           /* 896 int            */
#define SM_HIST  (SM_IDX + 3584)            /* 512 int            */
#define SM_RED   (SM_HIST + 2048)           /* 8 f32              */
#define SMEM_TOTAL (SM_RED + 32)            /* 228896             */

__device__ float g_whT[KCODES * DIM];   /* tf32(w)        */
__device__ float g_wlT[KCODES * DIM];   /* tf32(w - hi)   */
__device__ float g_wsq[KCODES];
__device__ int   g_counts[KCODES];
__device__ float g_msep[NCTA];

__device__ __forceinline__ uint32_t f2tf32(float v) {
    uint32_t r;
    asm("cvt.rna.tf32.f32 %0, %1;" : "=r"(r) : "f"(v));
    return r;
}

__device__ __forceinline__ void mma_tf32(float c[4], const uint32_t a[4],
                                         uint32_t b0, uint32_t b1)
{
    asm volatile(
        "mma.sync.aligned.m16n8k8.row.col.f32.tf32.tf32.f32 "
        "{%0,%1,%2,%3}, {%4,%5,%6,%7}, {%8,%9}, {%0,%1,%2,%3};"
        : "+f"(c[0]), "+f"(c[1]), "+f"(c[2]), "+f"(c[3])
        : "r"(a[0]), "r"(a[1]), "r"(a[2]), "r"(a[3]), "r"(b0), "r"(b1));
}

/* ---------------- prep: codebook tf32 split + norms + count reset -------- */
__global__ void __launch_bounds__(KCODES, 1)
vq_prep(const float* __restrict__ w)
{
    const int r = threadIdx.x;
    g_counts[r] = 0;
    const float* wr = w + r * DIM;
    float sq = 0.f;
    #pragma unroll
    for (int c = 0; c < DIM; c++) {
        float v = wr[c];
        sq = fmaf(v, v, sq);                       /* sequential: matches ref */
        uint32_t hb = f2tf32(v);
        float    hf = __uint_as_float(hb);
        uint32_t lb = f2tf32(v - hf);
        g_whT[r * DIM + c] = __uint_as_float(hb);
        g_wlT[r * DIM + c] = __uint_as_float(lb);
    }
    g_wsq[r] = sq;
}

/* ---------------- main ---------------- */
__global__ void __launch_bounds__(TPB, 1)
vq_main(const float* __restrict__ x, const float* __restrict__ w,
        float* __restrict__ out)
{
    extern __shared__ char smem[];
    float* s_wsq  = (float*)(smem + SM_WSQ);
    float* s_sx   = (float*)(smem + SM_SX);
    float* s_best = (float*)(smem + SM_BEST);
    int*   s_idx  = (int*)(smem + SM_IDX);
    int*   s_hist = (int*)(smem + SM_HIST);
    float* s_red  = (float*)(smem + SM_RED);

    const int tid  = threadIdx.x;
    const int wid  = tid >> 5;
    const int lane = tid & 31;
    const int qr   = lane >> 2;
    const int qp   = lane & 3;
    const int bid  = blockIdx.x;

    for (int i = tid; i < KCODES; i += TPB) { s_wsq[i] = g_wsq[i]; s_hist[i] = 0; }
    for (int i = tid; i < MAXSLOT * TILE_M; i += TPB) {
        s_best[i] = __int_as_float(0x7f800000);
        s_idx[i]  = 0;
    }
    __syncthreads();

    int nslots = 0;

    for (int half = 0; half < 2; half++) {
        const int nbase = half * NHALF;

        /* ---- pack B half into quads {bh0,bh1,bl0,bl1} ---- */
        for (int i = tid; i < NHALF * 32; i += TPB) {
            const int n = i >> 5, rr = i & 31;
            const int k = rr >> 2, c = rr & 3;
            const float* ph = g_whT + (size_t)(nbase + n) * DIM + k * 8 + c;
            const float* pl = g_wlT + (size_t)(nbase + n) * DIM + k * 8 + c;
            float4 q4 = make_float4(ph[0], ph[4], pl[0], pl[4]);
            *(float4*)(smem + SM_B + (size_t)(n * 36 + rr) * 16) = q4;
        }
        __syncthreads();

        int slot = 0;
        for (int tile = bid; tile < NTILES; tile += NCTA, slot++) {
            const int T0 = tile * TILE_M;

            /* ---- gather + tf32-split tokens (threads 0..127) ---- */
            if (tid < TILE_M) {
                const int b  = T0 >> 12;
                const int hw = (T0 & 4095) + tid;
                const float* xb = x + (size_t)b * (DIM * 4096) + hw;
                float* ah = (float*)(smem + SM_AH) + tid * 68 + ((tid >> 3) & 3);
                float* al = (float*)(smem + SM_AL) + tid * 68 + ((tid >> 3) & 3);
                float s = 0.f;
                #pragma unroll
                for (int c = 0; c < DIM; c++) {
                    float v = xb[(size_t)c * 4096];
                    s = fmaf(v, v, s);             /* sequential: matches ref */
                    uint32_t hb = f2tf32(v);
                    float    hf = __uint_as_float(hb);
                    uint32_t lb = f2tf32(v - hf);
                    ah[c] = __uint_as_float(hb);
                    al[c] = __uint_as_float(lb);
                }
                s_sx[tid] = s;
            }
            __syncthreads();

            /* ---- warp stripe: 16 tokens x 256 codes (this half) ---- */
            {
                const int rowA = wid * 16;
                const int r0 = rowA + qr, r1 = r0 + 8;
                const uint32_t* ph0 = (const uint32_t*)(smem + SM_AH) + r0 * 68 + ((r0 >> 3) & 3);
                const uint32_t* ph1 = (const uint32_t*)(smem + SM_AH) + r1 * 68 + ((r1 >> 3) & 3);
                const uint32_t* pl0 = (const uint32_t*)(smem + SM_AL) + r0 * 68 + ((r0 >> 3) & 3);
                const uint32_t* pl1 = (const uint32_t*)(smem + SM_AL) + r1 * 68 + ((r1 >> 3) & 3);

                uint32_t Ah[8][4], Al[8][4];
                #pragma unroll
                for (int k = 0; k < 8; k++) {
                    const int col = k * 8 + qp;
                    Ah[k][0] = ph0[col];     Ah[k][1] = ph1[col];
                    Ah[k][2] = ph0[col + 4]; Ah[k][3] = ph1[col + 4];
                    Al[k][0] = pl0[col];     Al[k][1] = pl1[col];
                    Al[k][2] = pl0[col + 4]; Al[k][3] = pl1[col + 4];
                }

                const float sx0 = s_sx[r0];
                const float sx1 = s_sx[r1];
                float best0 = __int_as_float(0x7f800000), best1 = best0;
                int   bi0 = 0, bi1 = 0;

                for (int n0 = 0; n0 < NHALF; n0 += 8) {
                    float c0[4] = {0.f, 0.f, 0.f, 0.f};
                    float c1[4] = {0.f, 0.f, 0.f, 0.f};
                    float c2[4] = {0.f, 0.f, 0.f, 0.f};
                    const uint4* pb = (const uint4*)(smem + SM_B)
                                      + (n0 + qr) * 36 + qp;
                    #pragma unroll
                    for (int k = 0; k < 8; k++) {
                        uint4 q = pb[k * 4];        /* bh0,bh1,bl0,bl1 */
                        mma_tf32(c0, Ah[k], q.x, q.y);   /* hi*hi */
                        mma_tf32(c1, Al[k], q.x, q.y);   /* lo*hi */
                        mma_tf32(c2, Ah[k], q.z, q.w);   /* hi*lo */
                    }
                    const int gj = nbase + n0 + 2 * qp;
                    const float w0 = s_wsq[gj], w1 = s_wsq[gj + 1];
                    const float d00 = fmaf(-2.f, (c0[0] + c1[0]) + c2[0], sx0) + w0;
                    const float d01 = fmaf(-2.f, (c0[1] + c1[1]) + c2[1], sx0) + w1;
                    const float d10 = fmaf(-2.f, (c0[2] + c1[2]) + c2[2], sx1) + w0;
                    const float d11 = fmaf(-2.f, (c0[3] + c1[3]) + c2[3], sx1) + w1;
                    if (d00 < best0) { best0 = d00; bi0 = gj; }
                    if (d01 < best0) { best0 = d01; bi0 = gj + 1; }
                    if (d10 < best1) { best1 = d10; bi1 = gj; }
                    if (d11 < best1) { best1 = d11; bi1 = gj + 1; }
                }

                /* cross-quad reduce, first-index tie-break */
                #pragma unroll
                for (int o = 1; o <= 2; o <<= 1) {
                    float ob0 = __shfl_xor_sync(0xffffffffu, best0, o);
                    int   oi0 = __shfl_xor_sync(0xffffffffu, bi0, o);
                    float ob1 = __shfl_xor_sync(0xffffffffu, best1, o);
                    int   oi1 = __shfl_xor_sync(0xffffffffu, bi1, o);
                    if (ob0 < best0 || (ob0 == best0 && oi0 < bi0)) { best0 = ob0; bi0 = oi0; }
                    if (ob1 < best1 || (ob1 == best1 && oi1 < bi1)) { best1 = ob1; bi1 = oi1; }
                }
                /* merge with running per-token best (halves ascend => ties keep stored) */
                if (qp == 0) {
                    const int o0 = slot * TILE_M + r0;
                    const int o1 = slot * TILE_M + r1;
                    if (best0 < s_best[o0]) { s_best[o0] = best0; s_idx[o0] = bi0; }
                    if (best1 < s_best[o1]) { s_best[o1] = best1; s_idx[o1] = bi1; }
                }
            }
            __syncthreads();
        }
        nslots = slot;
    }

    /* ---- epilogue: out = x_lin + (w[idx]-x_lin), fused MSE + hist ---- */
    float mse_acc = 0.f;
    for (int slot = 0; slot < nslots; slot++) {
        const int T0 = (bid + slot * NCTA) * TILE_M;
        if (tid < TILE_M) {
            const int g    = T0 + tid;
            const int bidx = s_idx[slot * TILE_M + tid];
            const float4* wb = (const float4*)(w + (size_t)bidx * DIM);
            const float4* xl = (const float4*)(x + (size_t)g * DIM);
            float4*       o4 = (float4*)(out + (size_t)g * DIM);
            float mse = 0.f;
            #pragma unroll
            for (int i = 0; i < DIM / 4; i++) {
                float4 wv = wb[i];
                float4 xv = xl[i];
                float d0 = wv.x - xv.x, d1 = wv.y - xv.y;
                float d2 = wv.z - xv.z, d3 = wv.w - xv.w;
                mse = fmaf(d0, d0, mse); mse = fmaf(d1, d1, mse);
                mse = fmaf(d2, d2, mse); mse = fmaf(d3, d3, mse);
                float4 ov;
                ov.x = xv.x + d0; ov.y = xv.y + d1;
                ov.z = xv.z + d2; ov.w = xv.w + d3;
                o4[i] = ov;
            }
            mse_acc += mse;
            atomicAdd(&s_hist[bidx], 1);
        }
    }
    __syncthreads();

    /* ---- block MSE reduce (warps 0..3 hold data) ---- */
    #pragma unroll
    for (int o = 16; o > 0; o >>= 1)
        mse_acc += __shfl_xor_sync(0xffffffffu, mse_acc, o);
    if (lane == 0 && wid < 4) s_red[wid] = mse_acc;
    __syncthreads();
    if (tid == 0)
        g_msep[bid] = s_red[0] + s_red[1] + s_red[2] + s_red[3];

    /* ---- flush histogram ---- */
    for (int i = tid; i < KCODES; i += TPB) {
        int c = s_hist[i];
        if (c) atomicAdd(&g_counts[i], c);
    }
}

/* ---------------- final scalars ---------------- */
__global__ void __launch_bounds__(512, 1)
vq_final(float* __restrict__ out)
{
    __shared__ float sred[16];
    const int tid = threadIdx.x;

    float m = (tid < NCTA) ? g_msep[tid] : 0.f;
    #pragma unroll
    for (int o = 16; o > 0; o >>= 1)
        m += __shfl_xor_sync(0xffffffffu, m, o);
    if ((tid & 31) == 0) sred[tid >> 5] = m;
    __syncthreads();
    float mt = 0.f;
    if (tid == 0) {
        #pragma unroll
        for (int i = 0; i < 16; i++) mt += sred[i];
    }
    __syncthreads();

    float p = (float)g_counts[tid] * (1.0f / (float)TOKENS);
    float e = p * logf(p + 1e-10f);
    #pragma unroll
    for (int o = 16; o > 0; o >>= 1)
        e += __shfl_xor_sync(0xffffffffu, e, o);
    if ((tid & 31) == 0) sred[tid >> 5] = e;
    __syncthreads();
    if (tid == 0) {
        float et = 0.f;
        #pragma unroll
        for (int i = 0; i < 16; i++) et += sred[i];
        out[(size_t)TOKENS * DIM]     = 1.25f * (mt / (float)(TOKENS * DIM));
        out[(size_t)TOKENS * DIM + 1] = expf(-et);
    }
}

extern "C" void kernel_launch(void* const* d_in, const int* in_sizes, int n_in,
                              void* d_out, int out_size)
{
    const float* x = (const float*)d_in[0];
    const float* w = (const float*)d_in[1];
    if (n_in >= 2 && in_sizes[0] == KCODES * DIM && in_sizes[1] == TOKENS * DIM) {
        const float* t = x; x = w; w = t;
    }
    float* out = (float*)d_out;

    (void)cudaFuncSetAttribute(vq_main,
                               cudaFuncAttributeMaxDynamicSharedMemorySize,
                               SMEM_TOTAL);

    vq_prep<<<1, KCODES>>>(w);
    vq_main<<<NCTA, TPB, SMEM_TOTAL>>>(x, w, out);
    vq_final<<<1, 512>>>(out);
}

// round 11
// speedup vs baseline: 1.5339x; 1.1138x over previous
#include <cuda_runtime.h>
#include <cstdint>

#define TOKENS  131072
#define KCODES  512
#define DIM     64
#define TILE_M  128
#define NTILES  (TOKENS / TILE_M)   /* 1024 */
#define NCTA    148
#define TPB     256

#define SROW    72                  /* floats per smem row (288 B) */
#define SROWB   (SROW * 4)

/* ---- smem layout (bytes) ---- */
#define SM_B     0                           /* 512 x 288B raw f32 pairs */
#define SM_A     (KCODES * SROWB)            /* 147456: 128 x 288B       */
#define SM_WSQ   (SM_A + TILE_M * SROWB)     /* 184320: 512 f32          */
#define SM_SX    (SM_WSQ + 2048)             /* 128 f32                  */
#define SM_SIDX  (SM_SX + 512)               /* 128 int                  */
#define SM_HIST  (SM_SIDX + 512)             /* 512 int                  */
#define SM_RED   (SM_HIST + 2048)            /* 8 f32                    */
#define SMEM_TOTAL (SM_RED + 32)             /* 189472                   */

__device__ int   g_counts[KCODES];
__device__ float g_msep[NCTA];

__device__ __forceinline__ uint32_t f2tf32(float v) {
    uint32_t r;
    asm("cvt.rna.tf32.f32 %0, %1;" : "=r"(r) : "f"(v));
    return r;
}
__device__ __forceinline__ void tf32split(float v, uint32_t& h, uint32_t& l) {
    h = f2tf32(v);
    l = f2tf32(v - __uint_as_float(h));
}

__device__ __forceinline__ void mma_tf32(float c[4], const uint32_t a[4],
                                         uint32_t b0, uint32_t b1)
{
    asm volatile(
        "mma.sync.aligned.m16n8k8.row.col.f32.tf32.tf32.f32 "
        "{%0,%1,%2,%3}, {%4,%5,%6,%7}, {%8,%9}, {%0,%1,%2,%3};"
        : "+f"(c[0]), "+f"(c[1]), "+f"(c[2]), "+f"(c[3])
        : "r"(a[0]), "r"(a[1]), "r"(a[2]), "r"(a[3]), "r"(b0), "r"(b1));
}

__global__ void __launch_bounds__(KCODES, 1) vq_init()
{
    g_counts[threadIdx.x] = 0;
}

/* ---------------- main (persistent, 148 CTAs) ---------------- */
__global__ void __launch_bounds__(TPB, 1)
vq_main(const float* __restrict__ x, const float* __restrict__ w,
        float* __restrict__ out)
{
    extern __shared__ char smem[];
    float* s_wsq  = (float*)(smem + SM_WSQ);
    float* s_sx   = (float*)(smem + SM_SX);
    int*   s_sidx = (int*)(smem + SM_SIDX);
    int*   s_hist = (int*)(smem + SM_HIST);
    float* s_red  = (float*)(smem + SM_RED);

    const int tid  = threadIdx.x;
    const int wid  = tid >> 5;
    const int lane = tid & 31;
    const int qr   = lane >> 2;
    const int qp   = lane & 3;
    const int bid  = blockIdx.x;

    for (int i = tid; i < KCODES; i += TPB) s_hist[i] = 0;

    /* ---- B load: raw f32 codebook as (c, c+4) float2 pairs + wsq chain ---- */
    #pragma unroll 1
    for (int r = tid; r < KCODES; r += TPB) {
        const float* wr = w + (size_t)r * DIM;
        float2* br = (float2*)(smem + SM_B + (size_t)r * SROWB);
        float sq = 0.f;
        #pragma unroll
        for (int g8 = 0; g8 < 8; g8++) {
            float4 v0 = *(const float4*)(wr + g8 * 8);
            float4 v1 = *(const float4*)(wr + g8 * 8 + 4);
            sq = fmaf(v0.x, v0.x, sq); sq = fmaf(v0.y, v0.y, sq);
            sq = fmaf(v0.z, v0.z, sq); sq = fmaf(v0.w, v0.w, sq);
            sq = fmaf(v1.x, v1.x, sq); sq = fmaf(v1.y, v1.y, sq);
            sq = fmaf(v1.z, v1.z, sq); sq = fmaf(v1.w, v1.w, sq);
            br[g8 * 4 + 0] = make_float2(v0.x, v1.x);
            br[g8 * 4 + 1] = make_float2(v0.y, v1.y);
            br[g8 * 4 + 2] = make_float2(v0.z, v1.z);
            br[g8 * 4 + 3] = make_float2(v0.w, v1.w);
        }
        s_wsq[r] = sq;
    }
    __syncthreads();

    float mse_acc = 0.f;

    #pragma unroll 1
    for (int tile = bid; tile < NTILES; tile += NCTA) {
        const int T0 = tile * TILE_M;

        /* ---- gather tokens (threads 0..127), raw pairs + s chain ---- */
        if (tid < TILE_M) {
            const int b  = T0 >> 12;
            const int hw = (T0 & 4095) + tid;
            const float* xb = x + (size_t)b * (DIM * 4096) + hw;
            float2* ar = (float2*)(smem + SM_A + (size_t)tid * SROWB);
            float s = 0.f;
            #pragma unroll
            for (int g8 = 0; g8 < 8; g8++) {
                float v[8];
                #pragma unroll
                for (int j = 0; j < 8; j++)
                    v[j] = xb[(size_t)(g8 * 8 + j) * 4096];
                #pragma unroll
                for (int j = 0; j < 8; j++) s = fmaf(v[j], v[j], s);
                #pragma unroll
                for (int j = 0; j < 4; j++)
                    ar[g8 * 4 + j] = make_float2(v[j], v[j + 4]);
            }
            s_sx[tid] = s;
        }
        __syncthreads();

        /* ---- warp stripe: 16 tokens x 512 codes ---- */
        {
            const int r0 = wid * 16 + qr, r1 = r0 + 8;
            const float2* pa0 = (const float2*)(smem + SM_A + (size_t)r0 * SROWB) + qp;
            const float2* pa1 = (const float2*)(smem + SM_A + (size_t)r1 * SROWB) + qp;

            uint32_t Ah[8][4], Al[8][4];
            #pragma unroll
            for (int k = 0; k < 8; k++) {
                float2 p0 = pa0[k * 4];
                float2 p1 = pa1[k * 4];
                tf32split(p0.x, Ah[k][0], Al[k][0]);
                tf32split(p1.x, Ah[k][1], Al[k][1]);
                tf32split(p0.y, Ah[k][2], Al[k][2]);
                tf32split(p1.y, Ah[k][3], Al[k][3]);
            }

            const float sx0 = s_sx[r0];
            const float sx1 = s_sx[r1];
            float best0 = __int_as_float(0x7f800000), best1 = best0;
            int   bi0 = 0, bi1 = 0;

            #pragma unroll 2
            for (int n0 = 0; n0 < KCODES; n0 += 8) {
                float c0[4] = {0.f, 0.f, 0.f, 0.f};
                float c1[4] = {0.f, 0.f, 0.f, 0.f};
                float c2[4] = {0.f, 0.f, 0.f, 0.f};
                const float2* pb =
                    (const float2*)(smem + SM_B + (size_t)(n0 + qr) * SROWB) + qp;
                #pragma unroll
                for (int k = 0; k < 8; k++) {
                    float2 bq = pb[k * 4];
                    uint32_t bh0, bl0, bh1, bl1;
                    tf32split(bq.x, bh0, bl0);
                    tf32split(bq.y, bh1, bl1);
                    mma_tf32(c0, Ah[k], bh0, bh1);   /* hi*hi */
                    mma_tf32(c1, Al[k], bh0, bh1);   /* lo*hi */
                    mma_tf32(c2, Ah[k], bl0, bl1);   /* hi*lo */
                }
                const int gj = n0 + 2 * qp;
                const float2 wsq2 = *(const float2*)(s_wsq + gj);   /* LDS.64 */
                const float d00 = fmaf(-2.f, (c0[0] + c1[0]) + c2[0], sx0) + wsq2.x;
                const float d01 = fmaf(-2.f, (c0[1] + c1[1]) + c2[1], sx0) + wsq2.y;
                const float d10 = fmaf(-2.f, (c0[2] + c1[2]) + c2[2], sx1) + wsq2.x;
                const float d11 = fmaf(-2.f, (c0[3] + c1[3]) + c2[3], sx1) + wsq2.y;
                if (d00 < best0) { best0 = d00; bi0 = gj; }
                if (d01 < best0) { best0 = d01; bi0 = gj + 1; }
                if (d10 < best1) { best1 = d10; bi1 = gj; }
                if (d11 < best1) { best1 = d11; bi1 = gj + 1; }
            }

            /* cross-quad reduce, first-index tie-break */
            #pragma unroll
            for (int o = 1; o <= 2; o <<= 1) {
                float ob0 = __shfl_xor_sync(0xffffffffu, best0, o);
                int   oi0 = __shfl_xor_sync(0xffffffffu, bi0, o);
                float ob1 = __shfl_xor_sync(0xffffffffu, best1, o);
                int   oi1 = __shfl_xor_sync(0xffffffffu, bi1, o);
                if (ob0 < best0 || (ob0 == best0 && oi0 < bi0)) { best0 = ob0; bi0 = oi0; }
                if (ob1 < best1 || (ob1 == best1 && oi1 < bi1)) { best1 = ob1; bi1 = oi1; }
            }
            if (qp == 0) { s_sidx[r0] = bi0; s_sidx[r1] = bi1; }
        }
        __syncthreads();

        /* ---- epilogue: out = x_lin + (w[idx]-x_lin), fused MSE + hist ---- */
        if (tid < TILE_M) {
            const int g    = T0 + tid;
            const int bidx = s_sidx[tid];
            const float4* wb = (const float4*)(w + (size_t)bidx * DIM);
            const float4* xl = (const float4*)(x + (size_t)g * DIM);
            float4*       o4 = (float4*)(out + (size_t)g * DIM);
            float mse = 0.f;
            #pragma unroll
            for (int i = 0; i < DIM / 4; i++) {
                float4 wv = wb[i];
                float4 xv = xl[i];
                float d0 = wv.x - xv.x, d1 = wv.y - xv.y;
                float d2 = wv.z - xv.z, d3 = wv.w - xv.w;
                mse = fmaf(d0, d0, mse); mse = fmaf(d1, d1, mse);
                mse = fmaf(d2, d2, mse); mse = fmaf(d3, d3, mse);
                float4 ov;
                ov.x = xv.x + d0; ov.y = xv.y + d1;
                ov.z = xv.z + d2; ov.w = xv.w + d3;
                o4[i] = ov;
            }
            mse_acc += mse;
            atomicAdd(&s_hist[bidx], 1);
        }
        __syncthreads();
    }

    /* ---- block MSE reduce (warps 0..3 hold data) ---- */
    #pragma unroll
    for (int o = 16; o > 0; o >>= 1)
        mse_acc += __shfl_xor_sync(0xffffffffu, mse_acc, o);
    if (lane == 0 && wid < 4) s_red[wid] = mse_acc;
    __syncthreads();
    if (tid == 0)
        g_msep[bid] = s_red[0] + s_red[1] + s_red[2] + s_red[3];

    /* ---- flush histogram ---- */
    for (int i = tid; i < KCODES; i += TPB) {
        int c = s_hist[i];
        if (c) atomicAdd(&g_counts[i], c);
    }
}

/* ---------------- final scalars ---------------- */
__global__ void __launch_bounds__(512, 1)
vq_final(float* __restrict__ out)
{
    __shared__ float sred[16];
    const int tid = threadIdx.x;

    float m = (tid < NCTA) ? g_msep[tid] : 0.f;
    #pragma unroll
    for (int o = 16; o > 0; o >>= 1)
        m += __shfl_xor_sync(0xffffffffu, m, o);
    if ((tid & 31) == 0) sred[tid >> 5] = m;
    __syncthreads();
    float mt = 0.f;
    if (tid == 0) {
        #pragma unroll
        for (int i = 0; i < 16; i++) mt += sred[i];
    }
    __syncthreads();

    float p = (float)g_counts[tid] * (1.0f / (float)TOKENS);
    float e = p * logf(p + 1e-10f);
    #pragma unroll
    for (int o = 16; o > 0; o >>= 1)
        e += __shfl_xor_sync(0xffffffffu, e, o);
    if ((tid & 31) == 0) sred[tid >> 5] = e;
    __syncthreads();
    if (tid == 0) {
        float et = 0.f;
        #pragma unroll
        for (int i = 0; i < 16; i++) et += sred[i];
        out[(size_t)TOKENS * DIM]     = 1.25f * (mt / (float)(TOKENS * DIM));
        out[(size_t)TOKENS * DIM + 1] = expf(-et);
    }
}

extern "C" void kernel_launch(void* const* d_in, const int* in_sizes, int n_in,
                              void* d_out, int out_size)
{
    const float* x = (const float*)d_in[0];
    const float* w = (const float*)d_in[1];
    if (n_in >= 2 && in_sizes[0] == KCODES * DIM && in_sizes[1] == TOKENS * DIM) {
        const float* t = x; x = w; w = t;
    }
    float* out = (float*)d_out;

    (void)cudaFuncSetAttribute(vq_main,
                               cudaFuncAttributeMaxDynamicSharedMemorySize,
                               SMEM_TOTAL);

    vq_init<<<1, KCODES>>>();
    vq_main<<<NCTA, TPB, SMEM_TOTAL>>>(x, w, out);
    vq_final<<<1, 512>>>(out);
}